// round 2
// baseline (speedup 1.0000x reference)
#include <cuda_runtime.h>
#include <math.h>

// Problem shapes (fixed by setup_inputs)
#define S_DIM 1024
#define B_DIM 2
#define D_DIM 1024
#define LP1   4            // 1 + L layers
#define H_DIM 16
#define HD    64           // head dim
#define BHD   (B_DIM * H_DIM)          // 32
#define ROWS  (B_DIM * D_DIM)          // 2048 floats per s-row (= BH*HD)
#define M_X   (S_DIM * B_DIM)          // 2048
#define M_LO  ((LP1 - 1) * S_DIM * B_DIM)  // 6144

// Scratch (static device allocations — allowed; no cudaMalloc anywhere)
__device__ float g_Q[(size_t)M_X * D_DIM];
__device__ float g_K[(size_t)LP1 * M_X * D_DIM];
__device__ float g_V[(size_t)LP1 * M_X * D_DIM];
__device__ float g_C[(size_t)M_X * D_DIM];

// ---------------------------------------------------------------------------
// Batched SGEMM:  C_z[M,N] = A[M,K] @ W_z[N,K]^T + bias_z,  K = N = D_DIM.
// 128x128 block, BK=8, 256 threads, 8x8 per-thread tile, reg prefetch.
// blockIdx.z selects output set (lets one launch fill the chip).
// ---------------------------------------------------------------------------
#define MAXB 3
struct GemmOuts {
    const float* W[MAXB];
    const float* bias[MAXB];
    float*       C[MAXB];
};

__global__ void __launch_bounds__(256) gemm_tn(const float* __restrict__ A,
                                               GemmOuts outs) {
    const int K = D_DIM;
    const int N = D_DIM;
    const float* __restrict__ W    = outs.W[blockIdx.z];
    const float* __restrict__ bias = outs.bias[blockIdx.z];
    float* __restrict__ Cout       = outs.C[blockIdx.z];

    __shared__ float As[8][128];
    __shared__ float Ws[8][128];

    const int bm  = blockIdx.y * 128;
    const int bn  = blockIdx.x * 128;
    const int tid = threadIdx.x;

    const int arow  = tid >> 1;         // 0..127
    const int acol4 = (tid & 1) * 4;    // 0 or 4

    const float* Ag = A + (size_t)(bm + arow) * K + acol4;
    const float* Wg = W + (size_t)(bn + arow) * K + acol4;

    const int tx = tid & 15;            // n-dir (x8)
    const int ty = tid >> 4;            // m-dir (x8)

    float acc[8][8];
#pragma unroll
    for (int i = 0; i < 8; ++i)
#pragma unroll
        for (int j = 0; j < 8; ++j) acc[i][j] = 0.f;

    // prefetch first tile
    float4 av = *(const float4*)(Ag);
    float4 wv = *(const float4*)(Wg);

    for (int k0 = 0; k0 < K; k0 += 8) {
        __syncthreads();
        As[acol4 + 0][arow] = av.x;
        As[acol4 + 1][arow] = av.y;
        As[acol4 + 2][arow] = av.z;
        As[acol4 + 3][arow] = av.w;
        Ws[acol4 + 0][arow] = wv.x;
        Ws[acol4 + 1][arow] = wv.y;
        Ws[acol4 + 2][arow] = wv.z;
        Ws[acol4 + 3][arow] = wv.w;
        __syncthreads();

        if (k0 + 8 < K) {               // prefetch next tile (hidden by compute)
            av = *(const float4*)(Ag + k0 + 8);
            wv = *(const float4*)(Wg + k0 + 8);
        }

#pragma unroll
        for (int kk = 0; kk < 8; ++kk) {
            float a[8], w[8];
            *(float4*)(a + 0) = *(const float4*)&As[kk][ty * 8 + 0];
            *(float4*)(a + 4) = *(const float4*)&As[kk][ty * 8 + 4];
            *(float4*)(w + 0) = *(const float4*)&Ws[kk][tx * 8 + 0];
            *(float4*)(w + 4) = *(const float4*)&Ws[kk][tx * 8 + 4];
#pragma unroll
            for (int i = 0; i < 8; ++i)
#pragma unroll
                for (int j = 0; j < 8; ++j)
                    acc[i][j] += a[i] * w[j];
        }
    }

    // epilogue: add bias, store
#pragma unroll
    for (int i = 0; i < 8; ++i) {
        const int row = bm + ty * 8 + i;
        float* crow = Cout + (size_t)row * N + bn + tx * 8;
#pragma unroll
        for (int j = 0; j < 8; j += 4) {
            float4 b4 = *(const float4*)(bias + bn + tx * 8 + j);
            float4 o;
            o.x = acc[i][j + 0] + b4.x;
            o.y = acc[i][j + 1] + b4.y;
            o.z = acc[i][j + 2] + b4.z;
            o.w = acc[i][j + 3] + b4.w;
            *(float4*)(crow + j) = o;
        }
    }
}

// ---------------------------------------------------------------------------
// Layer-wise attention. One thread per query row (q + acc in registers),
// K/V tiles (64 keys x 64 dim) staged in shared, online softmax per layer,
// layer-weighted accumulation into g_C (global RMW keeps regs bounded).
// Grid: (BH, S/128); block: 128 threads.
// ---------------------------------------------------------------------------
__global__ void __launch_bounds__(128) attn_kernel(
    const float* __restrict__ Q, const float* __restrict__ Kg,
    const float* __restrict__ Vg, const float* __restrict__ lw_in,
    float* __restrict__ Cc) {
    const int bh   = blockIdx.x;
    const int t    = threadIdx.x;
    const int srow = blockIdx.y * 128 + t;

    __shared__ float Ks[64][HD];
    __shared__ float Vs[64][HD];

    // q row -> registers (16 x float4)
    float q[HD];
    {
        const float4* qp = (const float4*)(Q + (size_t)srow * ROWS + bh * HD);
#pragma unroll
        for (int i = 0; i < HD / 4; ++i) ((float4*)q)[i] = qp[i];
    }

    // softmax over layer weights (4 values, redundant per thread)
    float lw[LP1];
    {
        float l0 = lw_in[0], l1 = lw_in[1], l2 = lw_in[2], l3 = lw_in[3];
        float mx = fmaxf(fmaxf(l0, l1), fmaxf(l2, l3));
        float e0 = expf(l0 - mx), e1 = expf(l1 - mx);
        float e2 = expf(l2 - mx), e3 = expf(l3 - mx);
        float inv = 1.f / (e0 + e1 + e2 + e3);
        lw[0] = e0 * inv; lw[1] = e1 * inv; lw[2] = e2 * inv; lw[3] = e3 * inv;
    }

    const float sc = 0.125f * 1.44269504088896340736f;  // hd^-0.5 * log2(e)

    for (int l = 0; l < LP1; ++l) {
        const float* Kl = Kg + (size_t)l * M_X * D_DIM;
        const float* Vl = Vg + (size_t)l * M_X * D_DIM;

        float m = -1e30f, ssum = 0.f;
        float acc[HD];
#pragma unroll
        for (int d = 0; d < HD; ++d) acc[d] = 0.f;

        for (int kt = 0; kt < S_DIM; kt += 64) {
            __syncthreads();
            // cooperative load of 64x64 K and V tiles (float4, coalesced)
#pragma unroll
            for (int i = 0; i < 8; ++i) {
                int idx = i * 128 + t;           // 0..1023
                int j   = idx >> 4;              // key row in tile
                int dp  = (idx & 15) << 2;       // dim offset
                size_t goff = (size_t)(kt + j) * ROWS + bh * HD + dp;
                *(float4*)&Ks[j][dp] = *(const float4*)(Kl + goff);
                *(float4*)&Vs[j][dp] = *(const float4*)(Vl + goff);
            }
            __syncthreads();

            for (int j = 0; j < 64; ++j) {
                float s0 = 0.f, s1 = 0.f, s2 = 0.f, s3 = 0.f;
#pragma unroll
                for (int d = 0; d < HD; d += 4) {
                    s0 += q[d + 0] * Ks[j][d + 0];
                    s1 += q[d + 1] * Ks[j][d + 1];
                    s2 += q[d + 2] * Ks[j][d + 2];
                    s3 += q[d + 3] * Ks[j][d + 3];
                }
                float s = ((s0 + s1) + (s2 + s3)) * sc;
                if (s <= m) {                         // common path
                    float p = exp2f(s - m);
                    ssum += p;
#pragma unroll
                    for (int d = 0; d < HD; ++d) acc[d] += p * Vs[j][d];
                } else {                              // rare: new max
                    float r = exp2f(m - s);
                    ssum = ssum * r + 1.f;
#pragma unroll
                    for (int d = 0; d < HD; ++d) acc[d] = acc[d] * r + Vs[j][d];
                    m = s;
                }
            }
        }

        // layer-weighted accumulate into combined buffer
        const float w = lw[l] / ssum;
        float* cp = Cc + (size_t)srow * ROWS + bh * HD;
        if (l == 0) {
#pragma unroll
            for (int d = 0; d < HD; d += 4) {
                float4 o;
                o.x = w * acc[d + 0]; o.y = w * acc[d + 1];
                o.z = w * acc[d + 2]; o.w = w * acc[d + 3];
                *(float4*)(cp + d) = o;
            }
        } else {
#pragma unroll
            for (int d = 0; d < HD; d += 4) {
                float4 c = *(const float4*)(cp + d);
                c.x += w * acc[d + 0]; c.y += w * acc[d + 1];
                c.z += w * acc[d + 2]; c.w += w * acc[d + 3];
                *(float4*)(cp + d) = c;
            }
        }
    }
}

// ---------------------------------------------------------------------------
extern "C" void kernel_launch(void* const* d_in, const int* in_sizes, int n_in,
                              void* d_out, int out_size) {
    const float* x  = (const float*)d_in[0];
    const float* lo = (const float*)d_in[1];
    const float* Wq = (const float*)d_in[2];
    const float* bq = (const float*)d_in[3];
    const float* Wk = (const float*)d_in[4];
    const float* bk = (const float*)d_in[5];
    const float* Wv = (const float*)d_in[6];
    const float* bv = (const float*)d_in[7];
    const float* Wo = (const float*)d_in[8];
    const float* bo = (const float*)d_in[9];
    const float* lw = (const float*)d_in[10];
    float* out = (float*)d_out;

    float *Qp, *Kp, *Vp, *Cp;
    cudaGetSymbolAddress((void**)&Qp, g_Q);
    cudaGetSymbolAddress((void**)&Kp, g_K);
    cudaGetSymbolAddress((void**)&Vp, g_V);
    cudaGetSymbolAddress((void**)&Cp, g_C);

    const dim3 blk(256);

    // 1) x -> Q, K[0], V[0]   (z-batched: 3*128 = 384 blocks, fills the chip)
    {
        GemmOuts o;
        o.W[0] = Wq; o.bias[0] = bq; o.C[0] = Qp;
        o.W[1] = Wk; o.bias[1] = bk; o.C[1] = Kp;
        o.W[2] = Wv; o.bias[2] = bv; o.C[2] = Vp;
        dim3 grid(D_DIM / 128, M_X / 128, 3);
        gemm_tn<<<grid, blk>>>(x, o);
    }
    // 2) layer_outputs -> K[1..3], V[1..3]
    {
        GemmOuts o;
        o.W[0] = Wk; o.bias[0] = bk; o.C[0] = Kp + (size_t)M_X * D_DIM;
        o.W[1] = Wv; o.bias[1] = bv; o.C[1] = Vp + (size_t)M_X * D_DIM;
        o.W[2] = Wk; o.bias[2] = bk; o.C[2] = Kp + (size_t)M_X * D_DIM; // unused (z=2)
        dim3 grid(D_DIM / 128, M_LO / 128, 2);
        gemm_tn<<<grid, blk>>>(lo, o);
    }
    // 3) attention -> combined
    attn_kernel<<<dim3(BHD, S_DIM / 128), 128>>>(Qp, Kp, Vp, lw, Cp);
    // 4) combined @ Wo^T + bo -> out
    {
        GemmOuts o;
        o.W[0] = Wo; o.bias[0] = bo; o.C[0] = out;
        o.W[1] = Wo; o.bias[1] = bo; o.C[1] = out;
        o.W[2] = Wo; o.bias[2] = bo; o.C[2] = out;
        dim3 grid(D_DIM / 128, M_X / 128, 1);
        gemm_tn<<<grid, blk>>>(Cp, o);
    }
}